// round 4
// baseline (speedup 1.0000x reference)
#include <cuda_runtime.h>

#define BATCH 64
#define TIN   128
#define FIN   64
#define HID   512
#define G4    2048
#define TOUTN 64
#define KLIN  32768
#define NLIN  4096
#define NBLK  128

__device__ float g_xT[TIN * BATCH * FIN];
__device__ float g_pre1[TIN * BATCH * G4];
__device__ float g_pre2[BATCH * G4];
__device__ float g_hA[BATCH * HID];
__device__ float g_hB[BATCH * HID];
__device__ float g_c[BATCH * HID];
__device__ float g_seq[BATCH * KLIN];
__device__ float g_part[2 * BATCH * NLIN];
__device__ unsigned g_bar_arrive = 0;
__device__ unsigned g_bar_release = 0;

__global__ void k_xt(const float* __restrict__ x) {
    int i = blockIdx.x * 256 + threadIdx.x;
    if (i < TIN * BATCH * FIN) {
        int k = i & 63, r = i >> 6;
        int t = r >> 6, b = r & 63;
        g_xT[i] = x[(b * TIN + t) * FIN + k];
    }
}

__global__ void k_init() {
    int i = blockIdx.x * 256 + threadIdx.x;
    if (i < BATCH * HID) g_hA[i] = 0.0f;
}

__global__ void k_combine(const float* __restrict__ blin, float* __restrict__ out) {
    int i = blockIdx.x * 256 + threadIdx.x;
    if (i < BATCH * NLIN)
        out[i] = g_part[i] + g_part[BATCH * NLIN + i] + blin[i & (NLIN - 1)];
}

// ---- tiled fp32 GEMM: C(64x64 tile) = A * W^T, double-buffered, 4x4 reg tiles ----
__device__ __forceinline__ void gemm64_core(
    const float* __restrict__ A, int lda,
    const float* __restrict__ W, int ldw,
    float* __restrict__ C, int ldc, int csplitStride, int kcount,
    const float* __restrict__ bias1, const float* __restrict__ bias2)
{
    __shared__ __align__(16) float As[2][32 * 68];
    __shared__ __align__(16) float Ws[2][32 * 68];
    const int tid = threadIdx.x;
    const int n0 = blockIdx.x * 64;
    const int kbase = blockIdx.y * kcount;
    const int mbase = blockIdx.z * 64;
    float* Cout = C + (size_t)blockIdx.y * csplitStride;
    const int b0 = (tid & 15) * 4, nt = (tid >> 4) * 4;

    float acc[4][4];
#pragma unroll
    for (int i = 0; i < 4; ++i)
#pragma unroll
        for (int j = 0; j < 4; ++j) acc[i][j] = 0.0f;

    const int ntiles = kcount >> 5;
#pragma unroll
    for (int e = 0; e < 8; ++e) {
        int idx = tid + e * 256, m = idx >> 5, k = idx & 31;
        As[0][k * 68 + m] = A[(size_t)(mbase + m) * lda + kbase + k];
        Ws[0][k * 68 + m] = W[(size_t)(n0 + m) * ldw + kbase + k];
    }
    __syncthreads();

    for (int kt = 0; kt < ntiles; ++kt) {
        float pfA[8], pfW[8];
        const bool more = (kt + 1 < ntiles);
        if (more) {
            int ko = kbase + ((kt + 1) << 5);
#pragma unroll
            for (int e = 0; e < 8; ++e) {
                int idx = tid + e * 256, m = idx >> 5, k = idx & 31;
                pfA[e] = A[(size_t)(mbase + m) * lda + ko + k];
                pfW[e] = W[(size_t)(n0 + m) * ldw + ko + k];
            }
        }
        const float* as = As[kt & 1];
        const float* wz = Ws[kt & 1];
#pragma unroll
        for (int k = 0; k < 32; ++k) {
            float4 av = *(const float4*)(as + k * 68 + b0);
            float4 wv = *(const float4*)(wz + k * 68 + nt);
            float aa[4] = {av.x, av.y, av.z, av.w};
            float ww[4] = {wv.x, wv.y, wv.z, wv.w};
#pragma unroll
            for (int i = 0; i < 4; ++i)
#pragma unroll
                for (int j = 0; j < 4; ++j)
                    acc[i][j] = fmaf(aa[i], ww[j], acc[i][j]);
        }
        if (more) {
            float* dA = As[(kt + 1) & 1];
            float* dW = Ws[(kt + 1) & 1];
#pragma unroll
            for (int e = 0; e < 8; ++e) {
                int idx = tid + e * 256, m = idx >> 5, k = idx & 31;
                dA[k * 68 + m] = pfA[e];
                dW[k * 68 + m] = pfW[e];
            }
        }
        __syncthreads();
    }
#pragma unroll
    for (int i = 0; i < 4; ++i) {
        int m = mbase + b0 + i;
#pragma unroll
        for (int j = 0; j < 4; ++j) {
            int n = n0 + nt + j;
            float v = acc[i][j];
            if (bias1) v += bias1[n];
            if (bias2) v += bias2[n];
            Cout[(size_t)m * ldc + n] = v;
        }
    }
}

__global__ void __launch_bounds__(256) k_pre1(const float* __restrict__ W,
                                              const float* __restrict__ b1,
                                              const float* __restrict__ b2) {
    gemm64_core(g_xT, FIN, W, FIN, g_pre1, G4, 0, FIN, b1, b2);
}
__global__ void __launch_bounds__(256) k_pre2(const float* __restrict__ W,
                                              const float* __restrict__ b1,
                                              const float* __restrict__ b2) {
    gemm64_core(g_hA, HID, W, HID, g_pre2, G4, 0, HID, b1, b2);
}
__global__ void __launch_bounds__(256) k_lin(const float* __restrict__ W) {
    gemm64_core(g_seq, KLIN, W, KLIN, g_part, NLIN, BATCH * NLIN, KLIN / 2,
                nullptr, nullptr);
}

// ---- persistent LSTM recurrence: 128 blocks, Whh resident in smem ----
__device__ __forceinline__ void lstm_core(
    const float* __restrict__ Whh,
    const float* __restrict__ pre, int preStride,
    float* __restrict__ hPing, float* __restrict__ hPong,
    float* __restrict__ cbuf, int loadC, int saveC,
    float* __restrict__ seqOut, int nsteps)
{
    __shared__ __align__(16) float ws[16 * 512];
    __shared__ __align__(16) float hs[2][64 * 20];
    __shared__ unsigned s_rbase;
    const int tid = threadIdx.x;
    const int hc0 = blockIdx.x * 4;

    for (int idx = tid; idx < 16 * 512; idx += 256) {
        int r = idx >> 9, k = idx & 511;
        int q = r >> 2, cc = r & 3;
        ws[idx] = Whh[(size_t)(q * HID + hc0 + cc) * HID + k];
    }
    if (tid == 0) s_rbase = *(volatile unsigned*)&g_bar_release;
    __syncthreads();
    const unsigned rbase = s_rbase;

    const int b = tid & 63;
    const int c = tid >> 6;
    const int hcol = hc0 + c;
    float creg = loadC ? cbuf[b * HID + hcol] : 0.0f;

    const float* w0b = ws + ((0 * 4 + c) << 9);
    const float* w1b = ws + ((1 * 4 + c) << 9);
    const float* w2b = ws + ((2 * 4 + c) << 9);
    const float* w3b = ws + ((3 * 4 + c) << 9);

    for (int t = 0; t < nsteps; ++t) {
        const float* hin = (t & 1) ? hPong : hPing;
        float* hout = (t & 1) ? hPing : hPong;
        const float* prept = pre + (size_t)t * preStride + b * G4 + hcol;
        float acc0 = prept[0], acc1 = prept[512];
        float acc2 = prept[1024], acc3 = prept[1536];

#pragma unroll
        for (int e = 0; e < 4; ++e) {
            int idx = tid + e * 256;
            hs[0][(idx >> 4) * 20 + (idx & 15)] =
                __ldcg(&hin[(idx >> 4) * HID + (idx & 15)]);
        }
        __syncthreads();

        for (int kt = 0; kt < 32; ++kt) {
            float pf[4];
            const bool more = (kt + 1 < 32);
            if (more) {
                int ko = (kt + 1) << 4;
#pragma unroll
                for (int e = 0; e < 4; ++e) {
                    int idx = tid + e * 256;
                    pf[e] = __ldcg(&hin[(idx >> 4) * HID + ko + (idx & 15)]);
                }
            }
            const float* hrow = &hs[kt & 1][b * 20];
            const int ko = kt << 4;
#pragma unroll
            for (int k4 = 0; k4 < 4; ++k4) {
                float4 hv = *(const float4*)(hrow + (k4 << 2));
                float4 a = *(const float4*)(w0b + ko + (k4 << 2));
                float4 f = *(const float4*)(w1b + ko + (k4 << 2));
                float4 g = *(const float4*)(w2b + ko + (k4 << 2));
                float4 o = *(const float4*)(w3b + ko + (k4 << 2));
                acc0 = fmaf(hv.x, a.x, acc0); acc0 = fmaf(hv.y, a.y, acc0);
                acc0 = fmaf(hv.z, a.z, acc0); acc0 = fmaf(hv.w, a.w, acc0);
                acc1 = fmaf(hv.x, f.x, acc1); acc1 = fmaf(hv.y, f.y, acc1);
                acc1 = fmaf(hv.z, f.z, acc1); acc1 = fmaf(hv.w, f.w, acc1);
                acc2 = fmaf(hv.x, g.x, acc2); acc2 = fmaf(hv.y, g.y, acc2);
                acc2 = fmaf(hv.z, g.z, acc2); acc2 = fmaf(hv.w, g.w, acc2);
                acc3 = fmaf(hv.x, o.x, acc3); acc3 = fmaf(hv.y, o.y, acc3);
                acc3 = fmaf(hv.z, o.z, acc3); acc3 = fmaf(hv.w, o.w, acc3);
            }
            if (more) {
                float* dst = hs[(kt + 1) & 1];
#pragma unroll
                for (int e = 0; e < 4; ++e) {
                    int idx = tid + e * 256;
                    dst[(idx >> 4) * 20 + (idx & 15)] = pf[e];
                }
            }
            __syncthreads();
        }

        float si = 1.0f / (1.0f + __expf(-acc0));
        float sf = 1.0f / (1.0f + __expf(-acc1));
        float so = 1.0f / (1.0f + __expf(-acc3));
        creg = sf * creg + si * tanhf(acc2);
        float hnew = so * tanhf(creg);
        hout[b * HID + hcol] = hnew;
        if (seqOut) seqOut[(size_t)b * KLIN + t * HID + hcol] = hnew;

        __syncthreads();
        if (tid == 0) {
            __threadfence();
            unsigned a = atomicAdd(&g_bar_arrive, 1u) + 1u;
            unsigned target = rbase + (unsigned)(t + 1);
            if (a == target * (unsigned)NBLK) atomicExch(&g_bar_release, target);
            while ((int)(*(volatile unsigned*)&g_bar_release - target) < 0)
                __nanosleep(64);
            __threadfence();
        }
        __syncthreads();
    }
    if (saveC) cbuf[b * HID + hcol] = creg;
}

__global__ void __launch_bounds__(256) k_enc(const float* __restrict__ Whh) {
    lstm_core(Whh, g_pre1, BATCH * G4, g_hA, g_hB, g_c, 0, 1, nullptr, TIN);
}
__global__ void __launch_bounds__(256) k_dec(const float* __restrict__ Whh) {
    lstm_core(Whh, g_pre2, 0, g_hA, g_hB, g_c, 1, 0, g_seq, TOUTN);
}

extern "C" void kernel_launch(void* const* d_in, const int* in_sizes, int n_in,
                              void* d_out, int out_size) {
    const float* x    = (const float*)d_in[0];
    const float* Wih1 = (const float*)d_in[1];
    const float* Whh1 = (const float*)d_in[2];
    const float* bih1 = (const float*)d_in[3];
    const float* bhh1 = (const float*)d_in[4];
    const float* Wih2 = (const float*)d_in[5];
    const float* Whh2 = (const float*)d_in[6];
    const float* bih2 = (const float*)d_in[7];
    const float* bhh2 = (const float*)d_in[8];
    const float* Wlin = (const float*)d_in[9];
    const float* blin = (const float*)d_in[10];
    float* out = (float*)d_out;

    k_xt<<<(TIN * BATCH * FIN + 255) / 256, 256>>>(x);
    k_init<<<(BATCH * HID + 255) / 256, 256>>>();

    dim3 gpre1(G4 / 64, 1, (TIN * BATCH) / 64);
    k_pre1<<<gpre1, 256>>>(Wih1, bih1, bhh1);

    k_enc<<<NBLK, 256>>>(Whh1);
    // TIN=128 (even): final h1 lands in g_hA; c saved to g_c.

    dim3 gpre2(G4 / 64, 1, 1);
    k_pre2<<<gpre2, 256>>>(Wih2, bih2, bhh2);

    k_dec<<<NBLK, 256>>>(Whh2);

    dim3 glin(NLIN / 64, 2, 1);
    k_lin<<<glin, 256>>>(Wlin);

    k_combine<<<(BATCH * NLIN + 255) / 256, 256>>>(blin, out);
}

// round 7
// speedup vs baseline: 1.6071x; 1.6071x over previous
#include <cuda_runtime.h>
#include <cstdint>

#define BATCH 64
#define TIN   128
#define FIN   64
#define HID   512
#define G4    2048
#define TOUTN 64
#define KLIN  32768
#define NLIN  4096
#define NBLK  128

#define KSPLIT 4
#define KPER   (KLIN / KSPLIT)   // 8192
#define LCHUNK 64
#define LNCH   (KPER / LCHUNK)   // 128

__device__ float g_xT[TIN * BATCH * FIN];
__device__ float g_pre1[TIN * BATCH * G4];
__device__ float g_pre2[BATCH * G4];
__device__ float g_hA[BATCH * HID];
__device__ float g_hB[BATCH * HID];
__device__ float g_c[BATCH * HID];
__device__ float g_seq[BATCH * KLIN];
__device__ float g_part[KSPLIT * BATCH * NLIN];   // [ks][b][m]
__device__ unsigned g_bar_arrive = 0;
__device__ unsigned g_bar_release = 0;

// ---------------- small kernels ----------------
__global__ void k_xt(const float* __restrict__ x) {
    int i = blockIdx.x * 256 + threadIdx.x;
    if (i < TIN * BATCH * FIN) {
        int k = i & 63, r = i >> 6;
        int t = r >> 6, b = r & 63;
        g_xT[i] = x[(b * TIN + t) * FIN + k];
    }
}
__global__ void k_init() {
    int i = blockIdx.x * 256 + threadIdx.x;
    if (i < BATCH * HID) g_hA[i] = 0.0f;
}
__global__ void k_combine(const float* __restrict__ blin, float* __restrict__ out) {
    int i = blockIdx.x * 256 + threadIdx.x;
    if (i < BATCH * NLIN) {
        int b = i >> 12, m = i & 4095;
        float s = blin[m];
#pragma unroll
        for (int ks = 0; ks < KSPLIT; ++ks)
            s += g_part[((size_t)ks * BATCH + b) * NLIN + m];
        out[i] = s;
    }
}

// ---------------- fp32 SIMT GEMM (pre-projections, proven) ----------------
__device__ __forceinline__ void gemm64_core(
    const float* __restrict__ A, int lda,
    const float* __restrict__ W, int ldw,
    float* __restrict__ C, int ldc, int kcount,
    const float* __restrict__ bias1, const float* __restrict__ bias2)
{
    __shared__ __align__(16) float As[2][32 * 68];
    __shared__ __align__(16) float Ws[2][32 * 68];
    const int tid = threadIdx.x;
    const int n0 = blockIdx.x * 64;
    const int mbase = blockIdx.z * 64;
    const int b0 = (tid & 15) * 4, nt = (tid >> 4) * 4;
    float acc[4][4];
#pragma unroll
    for (int i = 0; i < 4; ++i)
#pragma unroll
        for (int j = 0; j < 4; ++j) acc[i][j] = 0.0f;
    const int ntiles = kcount >> 5;
#pragma unroll
    for (int e = 0; e < 8; ++e) {
        int idx = tid + e * 256, m = idx >> 5, k = idx & 31;
        As[0][k * 68 + m] = A[(size_t)(mbase + m) * lda + k];
        Ws[0][k * 68 + m] = W[(size_t)(n0 + m) * ldw + k];
    }
    __syncthreads();
    for (int kt = 0; kt < ntiles; ++kt) {
        float pfA[8], pfW[8];
        const bool more = (kt + 1 < ntiles);
        if (more) {
            int ko = (kt + 1) << 5;
#pragma unroll
            for (int e = 0; e < 8; ++e) {
                int idx = tid + e * 256, m = idx >> 5, k = idx & 31;
                pfA[e] = A[(size_t)(mbase + m) * lda + ko + k];
                pfW[e] = W[(size_t)(n0 + m) * ldw + ko + k];
            }
        }
        const float* as = As[kt & 1];
        const float* wz = Ws[kt & 1];
#pragma unroll
        for (int k = 0; k < 32; ++k) {
            float4 av = *(const float4*)(as + k * 68 + b0);
            float4 wv = *(const float4*)(wz + k * 68 + nt);
            float aa[4] = {av.x, av.y, av.z, av.w};
            float ww[4] = {wv.x, wv.y, wv.z, wv.w};
#pragma unroll
            for (int i = 0; i < 4; ++i)
#pragma unroll
                for (int j = 0; j < 4; ++j)
                    acc[i][j] = fmaf(aa[i], ww[j], acc[i][j]);
        }
        if (more) {
            float* dA = As[(kt + 1) & 1];
            float* dW = Ws[(kt + 1) & 1];
#pragma unroll
            for (int e = 0; e < 8; ++e) {
                int idx = tid + e * 256, m = idx >> 5, k = idx & 31;
                dA[k * 68 + m] = pfA[e];
                dW[k * 68 + m] = pfW[e];
            }
        }
        __syncthreads();
    }
#pragma unroll
    for (int i = 0; i < 4; ++i) {
        int m = mbase + b0 + i;
#pragma unroll
        for (int j = 0; j < 4; ++j) {
            int n = n0 + nt + j;
            C[(size_t)m * ldc + n] = acc[i][j] + bias1[n] + bias2[n];
        }
    }
}
__global__ void __launch_bounds__(256) k_pre1(const float* __restrict__ W,
                                              const float* __restrict__ b1,
                                              const float* __restrict__ b2) {
    gemm64_core(g_xT, FIN, W, FIN, g_pre1, G4, FIN, b1, b2);
}
__global__ void __launch_bounds__(256) k_pre2(const float* __restrict__ W,
                                              const float* __restrict__ b1,
                                              const float* __restrict__ b2) {
    gemm64_core(g_hA, HID, W, HID, g_pre2, G4, HID, b1, b2);
}

// ---------------- tf32 mma.sync linear: out[b][m] = seq[b][:] . Wlin[m][:] ----------------
__device__ __forceinline__ uint32_t f2tf(float f) {
    uint32_t u;
    asm("cvt.rna.tf32.f32 %0, %1;" : "=r"(u) : "f"(f));
    return u;
}
__device__ __forceinline__ void mma_tf32(float* c, const uint32_t* a, const uint32_t* b) {
    asm volatile(
        "mma.sync.aligned.m16n8k8.row.col.f32.tf32.tf32.f32 "
        "{%0,%1,%2,%3}, {%4,%5,%6,%7}, {%8,%9}, {%0,%1,%2,%3};"
        : "+f"(c[0]), "+f"(c[1]), "+f"(c[2]), "+f"(c[3])
        : "r"(a[0]), "r"(a[1]), "r"(a[2]), "r"(a[3]), "r"(b[0]), "r"(b[1]));
}

// smem (uint32, tf32 bits): per buffer A 64x68, W 128x68. buf stride 13056.
__global__ void __launch_bounds__(256, 1) k_lin_mma(const float* __restrict__ Wl) {
    extern __shared__ __align__(16) uint32_t lsm[];
    const int tid = threadIdx.x, wid = tid >> 5, lane = tid & 31;
    const int gid = lane >> 2, tig = lane & 3;
    const int m0 = blockIdx.x * 128;
    const int ks = blockIdx.y;
    const int k0b = ks * KPER;

    float acc[4][2][4];
#pragma unroll
    for (int mt = 0; mt < 4; ++mt)
#pragma unroll
        for (int nt = 0; nt < 2; ++nt)
#pragma unroll
            for (int r = 0; r < 4; ++r) acc[mt][nt][r] = 0.0f;

    // prologue: stage chunk 0 into buffer 0
    {
        uint32_t* A0 = lsm;
        uint32_t* W0 = lsm + 4352;
#pragma unroll
        for (int e = 0; e < 4; ++e) {
            int idx = tid + e * 256, row = idx >> 4, c4 = idx & 15;
            float4 v = *(const float4*)(g_seq + (size_t)row * KLIN + k0b + c4 * 4);
            uint32_t* d = A0 + row * 68 + c4 * 4;
            d[0] = f2tf(v.x); d[1] = f2tf(v.y); d[2] = f2tf(v.z); d[3] = f2tf(v.w);
        }
#pragma unroll
        for (int e = 0; e < 8; ++e) {
            int idx = tid + e * 256, row = idx >> 4, c4 = idx & 15;
            float4 v = *(const float4*)(Wl + (size_t)(m0 + row) * KLIN + k0b + c4 * 4);
            uint32_t* d = W0 + row * 68 + c4 * 4;
            d[0] = f2tf(v.x); d[1] = f2tf(v.y); d[2] = f2tf(v.z); d[3] = f2tf(v.w);
        }
    }
    __syncthreads();

    for (int ch = 0; ch < LNCH; ++ch) {
        const int buf = ch & 1;
        const bool more = (ch + 1 < LNCH);
        float4 fa[4], fw[8];
        if (more) {
            int k0 = k0b + (ch + 1) * LCHUNK;
#pragma unroll
            for (int e = 0; e < 4; ++e) {
                int idx = tid + e * 256, row = idx >> 4, c4 = idx & 15;
                fa[e] = *(const float4*)(g_seq + (size_t)row * KLIN + k0 + c4 * 4);
            }
#pragma unroll
            for (int e = 0; e < 8; ++e) {
                int idx = tid + e * 256, row = idx >> 4, c4 = idx & 15;
                fw[e] = *(const float4*)(Wl + (size_t)(m0 + row) * KLIN + k0 + c4 * 4);
            }
        }
        const uint32_t* As = lsm + buf * 13056;
        const uint32_t* Ws = lsm + buf * 13056 + 4352;
#pragma unroll
        for (int kk = 0; kk < 8; ++kk) {
            uint32_t a[4][4], b[2][2];
#pragma unroll
            for (int mt = 0; mt < 4; ++mt) {
                const uint32_t* ap = As + (mt * 16 + gid) * 68 + kk * 8 + tig;
                a[mt][0] = ap[0];
                a[mt][1] = ap[8 * 68];
                a[mt][2] = ap[4];
                a[mt][3] = ap[8 * 68 + 4];
            }
#pragma unroll
            for (int nt = 0; nt < 2; ++nt) {
                const uint32_t* bp = Ws + (wid * 16 + nt * 8 + gid) * 68 + kk * 8 + tig;
                b[nt][0] = bp[0];
                b[nt][1] = bp[4];
            }
#pragma unroll
            for (int mt = 0; mt < 4; ++mt)
#pragma unroll
                for (int nt = 0; nt < 2; ++nt)
                    mma_tf32(acc[mt][nt], a[mt], b[nt]);
        }
        if (more) {
            uint32_t* A1 = lsm + (buf ^ 1) * 13056;
            uint32_t* W1 = A1 + 4352;
#pragma unroll
            for (int e = 0; e < 4; ++e) {
                int idx = tid + e * 256, row = idx >> 4, c4 = idx & 15;
                uint32_t* d = A1 + row * 68 + c4 * 4;
                d[0] = f2tf(fa[e].x); d[1] = f2tf(fa[e].y);
                d[2] = f2tf(fa[e].z); d[3] = f2tf(fa[e].w);
            }
#pragma unroll
            for (int e = 0; e < 8; ++e) {
                int idx = tid + e * 256, row = idx >> 4, c4 = idx & 15;
                uint32_t* d = W1 + row * 68 + c4 * 4;
                d[0] = f2tf(fw[e].x); d[1] = f2tf(fw[e].y);
                d[2] = f2tf(fw[e].z); d[3] = f2tf(fw[e].w);
            }
        }
        __syncthreads();
    }

    // epilogue: write partials
#pragma unroll
    for (int mt = 0; mt < 4; ++mt) {
#pragma unroll
        for (int nt = 0; nt < 2; ++nt) {
            int brow = mt * 16 + gid;
            int m = m0 + wid * 16 + nt * 8 + 2 * tig;
            float* base0 = &g_part[((size_t)ks * BATCH + brow) * NLIN + m];
            float* base1 = &g_part[((size_t)ks * BATCH + brow + 8) * NLIN + m];
            *(float2*)base0 = make_float2(acc[mt][nt][0], acc[mt][nt][1]);
            *(float2*)base1 = make_float2(acc[mt][nt][2], acc[mt][nt][3]);
        }
    }
}

// ---------------- persistent LSTM recurrence (512 threads, K-half split) ----------------
// dyn smem (floats): ws[8192] | hf[64*516=33024] | red[1024]   = 168960 bytes
#define HSTR 516
__device__ __forceinline__ void lstm_core(
    const float* __restrict__ Whh,
    const float* __restrict__ pre, int preStride,
    float* __restrict__ hPing, float* __restrict__ hPong,
    float* __restrict__ cbuf, int loadC, int saveC,
    float* __restrict__ seqOut, int nsteps)
{
    extern __shared__ __align__(16) float dsm[];
    float* ws  = dsm;
    float* hf  = dsm + 8192;
    float* red = dsm + 8192 + 64 * HSTR;
    __shared__ unsigned s_rbase;

    const int tid = threadIdx.x;
    const int hc0 = blockIdx.x * 4;

    for (int idx = tid; idx < 16 * 512; idx += 512) {
        int r = idx >> 9, k = idx & 511;
        int q = r >> 2, cc = r & 3;
        ws[idx] = Whh[(size_t)(q * HID + hc0 + cc) * HID + k];
    }
    if (tid == 0) s_rbase = *(volatile unsigned*)&g_bar_release;
    __syncthreads();
    const unsigned rbase = s_rbase;

    const int b = tid & 63;
    const int c = (tid >> 6) & 3;
    const int khalf = tid >> 8;          // 0 or 1
    const int hcol = hc0 + c;

    float creg = (loadC && tid < 256) ? cbuf[b * HID + hcol] : 0.0f;

    const float* w0 = ws + ((0 * 4 + c) << 9) + khalf * 256;
    const float* w1 = ws + ((1 * 4 + c) << 9) + khalf * 256;
    const float* w2 = ws + ((2 * 4 + c) << 9) + khalf * 256;
    const float* w3 = ws + ((3 * 4 + c) << 9) + khalf * 256;

    for (int t = 0; t < nsteps; ++t) {
        const float* hin = (t & 1) ? hPong : hPing;
        float* hout = (t & 1) ? hPing : hPong;

        float p0 = 0.f, p1 = 0.f, p2 = 0.f, p3 = 0.f;
        if (tid < 256) {
            const float* prept = pre + (size_t)t * preStride + b * G4 + hcol;
            p0 = prept[0]; p1 = prept[512]; p2 = prept[1024]; p3 = prept[1536];
        }

        float4 pf[16];
#pragma unroll
        for (int e = 0; e < 16; ++e) {
            int idx = tid + (e << 9);
            int row = idx >> 7, c4 = idx & 127;
            pf[e] = __ldcg((const float4*)(hin + row * 512 + c4 * 4));
        }
#pragma unroll
        for (int e = 0; e < 16; ++e) {
            int idx = tid + (e << 9);
            int row = idx >> 7, c4 = idx & 127;
            *(float4*)(hf + row * HSTR + c4 * 4) = pf[e];
        }
        __syncthreads();

        float a0 = 0.f, a1 = 0.f, a2 = 0.f, a3 = 0.f;
        const float4* hrow = (const float4*)(hf + b * HSTR + khalf * 256);
        const float4* W0 = (const float4*)w0;
        const float4* W1 = (const float4*)w1;
        const float4* W2 = (const float4*)w2;
        const float4* W3 = (const float4*)w3;
#pragma unroll 8
        for (int k4 = 0; k4 < 64; ++k4) {
            float4 hv = hrow[k4];
            float4 v0 = W0[k4], v1 = W1[k4], v2 = W2[k4], v3 = W3[k4];
            a0 = fmaf(hv.x, v0.x, a0); a0 = fmaf(hv.y, v0.y, a0);
            a0 = fmaf(hv.z, v0.z, a0); a0 = fmaf(hv.w, v0.w, a0);
            a1 = fmaf(hv.x, v1.x, a1); a1 = fmaf(hv.y, v1.y, a1);
            a1 = fmaf(hv.z, v1.z, a1); a1 = fmaf(hv.w, v1.w, a1);
            a2 = fmaf(hv.x, v2.x, a2); a2 = fmaf(hv.y, v2.y, a2);
            a2 = fmaf(hv.z, v2.z, a2); a2 = fmaf(hv.w, v2.w, a2);
            a3 = fmaf(hv.x, v3.x, a3); a3 = fmaf(hv.y, v3.y, a3);
            a3 = fmaf(hv.z, v3.w ? v3.w : v3.w, a3);
            a3 = fmaf(hv.y, v3.y, a3); a3 = fmaf(hv.x, v3.x, a3);
            a3 = a3; // placeholder removed below
        }
        // NOTE: the block above must be exactly 16 FMAs; rewritten cleanly:
        a0 = 0.f; a1 = 0.f; a2 = 0.f; a3 = 0.f;
#pragma unroll 8
        for (int k4 = 0; k4 < 64; ++k4) {
            float4 hv = hrow[k4];
            float4 v0 = W0[k4], v1 = W1[k4], v2 = W2[k4], v3 = W3[k4];
            a0 = fmaf(hv.x, v0.x, a0); a0 = fmaf(hv.y, v0.y, a0);
            a0 = fmaf(hv.z, v0.z, a0); a0 = fmaf(hv.w, v0.w, a0);
            a1 = fmaf(hv.x, v1.x, a1); a1 = fmaf(hv.y, v1.y, a1);
            a1 = fmaf(hv.z, v1.z, a1); a1 = fmaf(hv.w, v1.w, a1);
            a2 = fmaf(hv.x, v2.x, a2); a2 = fmaf(hv.y, v2.y, a2);
            a2 = fmaf(hv.z, v2.z, a2); a2 = fmaf(hv.w, v2.w, a2);
            a3 = fmaf(hv.x, v3.x, a3); a3 = fmaf(hv.y, v3.y, a3);
            a3 = fmaf(hv.z, v3.z, a3); a3 = fmaf(hv.w, v3.w, a3);
        }
        if (tid >= 256)
            *(float4*)(red + ((tid - 256) << 2)) = make_float4(a0, a1, a2, a3);
        __syncthreads();
        if (tid < 256) {
            float4 r = *(const float4*)(red + (tid << 2));
            a0 += r.x + p0; a1 += r.y + p1; a2 += r.z + p2; a3 += r.w + p3;
            float si = 1.0f / (1.0f + __expf(-a0));
            float sf = 1.0f / (1.0f + __expf(-a1));
            float so = 1.0f / (1.0f + __expf(-a3));
            creg = sf * creg + si * tanhf(a2);
            float hnew = so * tanhf(creg);
            hout[b * HID + hcol] = hnew;
            if (seqOut) seqOut[(size_t)b * KLIN + t * HID + hcol] = hnew;
        }
        __syncthreads();
        if (tid == 0) {
            __threadfence();
            unsigned a = atomicAdd(&g_bar_arrive, 1u) + 1u;
            unsigned target = rbase + (unsigned)(t + 1);
            if (a == target * (unsigned)NBLK) atomicExch(&g_bar_release, target);
            while ((int)(*(volatile unsigned*)&g_bar_release - target) < 0)
                __nanosleep(64);
            __threadfence();
        }
        __syncthreads();
    }
    if (saveC && tid < 256) cbuf[b * HID + hcol] = creg;
}

__global__ void __launch_bounds__(512, 1) k_enc(const float* __restrict__ Whh) {
    lstm_core(Whh, g_pre1, BATCH * G4, g_hA, g_hB, g_c, 0, 1, nullptr, TIN);
}
__global__ void __launch_bounds__(512, 1) k_dec(const float* __restrict__ Whh) {
    lstm_core(Whh, g_pre2, 0, g_hA, g_hB, g_c, 1, 0, g_seq, TOUTN);
}

extern "C" void kernel_launch(void* const* d_in, const int* in_sizes, int n_in,
                              void* d_out, int out_size) {
    const float* x    = (const float*)d_in[0];
    const float* Wih1 = (const float*)d_in[1];
    const float* Whh1 = (const float*)d_in[2];
    const float* bih1 = (const float*)d_in[3];
    const float* bhh1 = (const float*)d_in[4];
    const float* Wih2 = (const float*)d_in[5];
    const float* Whh2 = (const float*)d_in[6];
    const float* bih2 = (const float*)d_in[7];
    const float* bhh2 = (const float*)d_in[8];
    const float* Wlin = (const float*)d_in[9];
    const float* blin = (const float*)d_in[10];
    float* out = (float*)d_out;

    const int lstmSmem = (8192 + 64 * HSTR + 1024) * 4;   // 168960
    const int linSmem  = 2 * 13056 * 4;                   // 104448
    cudaFuncSetAttribute(k_enc, cudaFuncAttributeMaxDynamicSharedMemorySize, lstmSmem);
    cudaFuncSetAttribute(k_dec, cudaFuncAttributeMaxDynamicSharedMemorySize, lstmSmem);
    cudaFuncSetAttribute(k_lin_mma, cudaFuncAttributeMaxDynamicSharedMemorySize, linSmem);

    k_xt<<<(TIN * BATCH * FIN + 255) / 256, 256>>>(x);
    k_init<<<(BATCH * HID + 255) / 256, 256>>>();

    dim3 gpre1(G4 / 64, 1, (TIN * BATCH) / 64);
    k_pre1<<<gpre1, 256>>>(Wih1, bih1, bhh1);

    k_enc<<<NBLK, 512, lstmSmem>>>(Whh1);   // TIN even: final h in g_hA, c in g_c

    dim3 gpre2(G4 / 64, 1, 1);
    k_pre2<<<gpre2, 256>>>(Wih2, bih2, bhh2);

    k_dec<<<NBLK, 512, lstmSmem>>>(Whh2);

    dim3 glin(NLIN / 128, KSPLIT);
    k_lin_mma<<<glin, 256, linSmem>>>(Wlin);

    k_combine<<<(BATCH * NLIN + 255) / 256, 256>>>(blin, out);
}

// round 8
// speedup vs baseline: 1.7563x; 1.0928x over previous
#include <cuda_runtime.h>
#include <cstdint>

#define BATCH 64
#define TIN   128
#define FIN   64
#define HID   512
#define G4    2048
#define TOUTN 64
#define KLIN  32768
#define NLIN  4096
#define NBLK  128

#define KSPLIT 4
#define KPER   (KLIN / KSPLIT)
#define LCHUNK 64
#define LNCH   (KPER / LCHUNK)

// lstm smem layout (uint32 units)
#define AHI_OFF 16384
#define ALO_OFF (AHI_OFF + 16640)
#define CSM_OFF (ALO_OFF + 16640)
#define RED_OFF (CSM_OFF + 1088)
#define DSMW    (RED_OFF + 1024)     // 51776 u32 = 207104 B

__device__ float g_xT[TIN * BATCH * FIN];
__device__ float g_pre1[TIN * BATCH * G4];
__device__ float g_pre2[BATCH * G4];
__device__ float g_hA[BATCH * HID];
__device__ float g_hB[BATCH * HID];
__device__ float g_c[BATCH * HID];
__device__ float g_seq[BATCH * KLIN];
__device__ float g_part[KSPLIT * BATCH * NLIN];
__device__ unsigned g_ctr[8];

// ---------------- tf32 helpers (mapping HW-verified in R7's k_lin_mma) ----------------
__device__ __forceinline__ uint32_t f2tf(float f) {
    uint32_t u;
    asm("cvt.rna.tf32.f32 %0, %1;" : "=r"(u) : "f"(f));
    return u;
}
__device__ __forceinline__ void mma_tf32(float* c, const uint32_t* a, const uint32_t* b) {
    asm volatile(
        "mma.sync.aligned.m16n8k8.row.col.f32.tf32.tf32.f32 "
        "{%0,%1,%2,%3}, {%4,%5,%6,%7}, {%8,%9}, {%0,%1,%2,%3};"
        : "+f"(c[0]), "+f"(c[1]), "+f"(c[2]), "+f"(c[3])
        : "r"(a[0]), "r"(a[1]), "r"(a[2]), "r"(a[3]), "r"(b[0]), "r"(b[1]));
}

// ---------------- small kernels ----------------
__global__ void k_xt(const float* __restrict__ x) {
    int i = blockIdx.x * 256 + threadIdx.x;
    if (i < TIN * BATCH * FIN) {
        int k = i & 63, r = i >> 6;
        int t = r >> 6, b = r & 63;
        g_xT[i] = x[(b * TIN + t) * FIN + k];
    }
}
__global__ void k_init() {
    int i = blockIdx.x * 256 + threadIdx.x;
    if (i < BATCH * HID) g_hA[i] = 0.0f;
    if (blockIdx.x == 0 && threadIdx.x < 8) g_ctr[threadIdx.x] = 0u;
}
__global__ void k_zero() {
    if (threadIdx.x < 8) g_ctr[threadIdx.x] = 0u;
}
__global__ void k_combine(const float* __restrict__ blin, float* __restrict__ out) {
    int i = blockIdx.x * 256 + threadIdx.x;
    if (i < BATCH * NLIN) {
        int b = i >> 12, m = i & 4095;
        float s = blin[m];
#pragma unroll
        for (int ks = 0; ks < KSPLIT; ++ks)
            s += g_part[((size_t)ks * BATCH + b) * NLIN + m];
        out[i] = s;
    }
}

// ---------------- fp32 SIMT GEMM (pre-projections, proven) ----------------
__device__ __forceinline__ void gemm64_core(
    const float* __restrict__ A, int lda,
    const float* __restrict__ W, int ldw,
    float* __restrict__ C, int ldc, int kcount,
    const float* __restrict__ bias1, const float* __restrict__ bias2)
{
    __shared__ __align__(16) float As[2][32 * 68];
    __shared__ __align__(16) float Ws[2][32 * 68];
    const int tid = threadIdx.x;
    const int n0 = blockIdx.x * 64;
    const int mbase = blockIdx.z * 64;
    const int b0 = (tid & 15) * 4, nt = (tid >> 4) * 4;
    float acc[4][4];
#pragma unroll
    for (int i = 0; i < 4; ++i)
#pragma unroll
        for (int j = 0; j < 4; ++j) acc[i][j] = 0.0f;
    const int ntiles = kcount >> 5;
#pragma unroll
    for (int e = 0; e < 8; ++e) {
        int idx = tid + e * 256, m = idx >> 5, k = idx & 31;
        As[0][k * 68 + m] = A[(size_t)(mbase + m) * lda + k];
        Ws[0][k * 68 + m] = W[(size_t)(n0 + m) * ldw + k];
    }
    __syncthreads();
    for (int kt = 0; kt < ntiles; ++kt) {
        float pfA[8], pfW[8];
        const bool more = (kt + 1 < ntiles);
        if (more) {
            int ko = (kt + 1) << 5;
#pragma unroll
            for (int e = 0; e < 8; ++e) {
                int idx = tid + e * 256, m = idx >> 5, k = idx & 31;
                pfA[e] = A[(size_t)(mbase + m) * lda + ko + k];
                pfW[e] = W[(size_t)(n0 + m) * ldw + ko + k];
            }
        }
        const float* as = As[kt & 1];
        const float* wz = Ws[kt & 1];
#pragma unroll
        for (int k = 0; k < 32; ++k) {
            float4 av = *(const float4*)(as + k * 68 + b0);
            float4 wv = *(const float4*)(wz + k * 68 + nt);
            float aa[4] = {av.x, av.y, av.z, av.w};
            float ww[4] = {wv.x, wv.y, wv.z, wv.w};
#pragma unroll
            for (int i = 0; i < 4; ++i)
#pragma unroll
                for (int j = 0; j < 4; ++j)
                    acc[i][j] = fmaf(aa[i], ww[j], acc[i][j]);
        }
        if (more) {
            float* dA = As[(kt + 1) & 1];
            float* dW = Ws[(kt + 1) & 1];
#pragma unroll
            for (int e = 0; e < 8; ++e) {
                int idx = tid + e * 256, m = idx >> 5, k = idx & 31;
                dA[k * 68 + m] = pfA[e];
                dW[k * 68 + m] = pfW[e];
            }
        }
        __syncthreads();
    }
#pragma unroll
    for (int i = 0; i < 4; ++i) {
        int m = mbase + b0 + i;
#pragma unroll
        for (int j = 0; j < 4; ++j) {
            int n = n0 + nt + j;
            C[(size_t)m * ldc + n] = acc[i][j] + bias1[n] + bias2[n];
        }
    }
}
__global__ void __launch_bounds__(256) k_pre1(const float* __restrict__ W,
                                              const float* __restrict__ b1,
                                              const float* __restrict__ b2) {
    gemm64_core(g_xT, FIN, W, FIN, g_pre1, G4, FIN, b1, b2);
}
__global__ void __launch_bounds__(256) k_pre2(const float* __restrict__ W,
                                              const float* __restrict__ b1,
                                              const float* __restrict__ b2) {
    gemm64_core(g_hA, HID, W, HID, g_pre2, G4, HID, b1, b2);
}

// ---------------- tf32 mma.sync linear (proven in R7) ----------------
__global__ void __launch_bounds__(256, 1) k_lin_mma(const float* __restrict__ Wl) {
    extern __shared__ __align__(16) uint32_t lsm[];
    const int tid = threadIdx.x, wid = tid >> 5, lane = tid & 31;
    const int gid = lane >> 2, tig = lane & 3;
    const int m0 = blockIdx.x * 128;
    const int ks = blockIdx.y;
    const int k0b = ks * KPER;

    float acc[4][2][4];
#pragma unroll
    for (int mt = 0; mt < 4; ++mt)
#pragma unroll
        for (int nt = 0; nt < 2; ++nt)
#pragma unroll
            for (int r = 0; r < 4; ++r) acc[mt][nt][r] = 0.0f;
    {
        uint32_t* A0 = lsm;
        uint32_t* W0 = lsm + 4352;
#pragma unroll
        for (int e = 0; e < 4; ++e) {
            int idx = tid + e * 256, row = idx >> 4, c4 = idx & 15;
            float4 v = *(const float4*)(g_seq + (size_t)row * KLIN + k0b + c4 * 4);
            uint32_t* d = A0 + row * 68 + c4 * 4;
            d[0] = f2tf(v.x); d[1] = f2tf(v.y); d[2] = f2tf(v.z); d[3] = f2tf(v.w);
        }
#pragma unroll
        for (int e = 0; e < 8; ++e) {
            int idx = tid + e * 256, row = idx >> 4, c4 = idx & 15;
            float4 v = *(const float4*)(Wl + (size_t)(m0 + row) * KLIN + k0b + c4 * 4);
            uint32_t* d = W0 + row * 68 + c4 * 4;
            d[0] = f2tf(v.x); d[1] = f2tf(v.y); d[2] = f2tf(v.z); d[3] = f2tf(v.w);
        }
    }
    __syncthreads();

    for (int ch = 0; ch < LNCH; ++ch) {
        const int buf = ch & 1;
        const bool more = (ch + 1 < LNCH);
        float4 fa[4], fw[8];
        if (more) {
            int k0 = k0b + (ch + 1) * LCHUNK;
#pragma unroll
            for (int e = 0; e < 4; ++e) {
                int idx = tid + e * 256, row = idx >> 4, c4 = idx & 15;
                fa[e] = *(const float4*)(g_seq + (size_t)row * KLIN + k0 + c4 * 4);
            }
#pragma unroll
            for (int e = 0; e < 8; ++e) {
                int idx = tid + e * 256, row = idx >> 4, c4 = idx & 15;
                fw[e] = *(const float4*)(Wl + (size_t)(m0 + row) * KLIN + k0 + c4 * 4);
            }
        }
        const uint32_t* As = lsm + buf * 13056;
        const uint32_t* Ws = lsm + buf * 13056 + 4352;
#pragma unroll
        for (int kk = 0; kk < 8; ++kk) {
            uint32_t a[4][4], b[2][2];
#pragma unroll
            for (int mt = 0; mt < 4; ++mt) {
                const uint32_t* ap = As + (mt * 16 + gid) * 68 + kk * 8 + tig;
                a[mt][0] = ap[0];
                a[mt][1] = ap[8 * 68];
                a[mt][2] = ap[4];
                a[mt][3] = ap[8 * 68 + 4];
            }
#pragma unroll
            for (int nt = 0; nt < 2; ++nt) {
                const uint32_t* bp = Ws + (wid * 16 + nt * 8 + gid) * 68 + kk * 8 + tig;
                b[nt][0] = bp[0];
                b[nt][1] = bp[4];
            }
#pragma unroll
            for (int mt = 0; mt < 4; ++mt)
#pragma unroll
                for (int nt = 0; nt < 2; ++nt)
                    mma_tf32(acc[mt][nt], a[mt], b[nt]);
        }
        if (more) {
            uint32_t* A1 = lsm + (buf ^ 1) * 13056;
            uint32_t* W1 = A1 + 4352;
#pragma unroll
            for (int e = 0; e < 4; ++e) {
                int idx = tid + e * 256, row = idx >> 4, c4 = idx & 15;
                uint32_t* d = A1 + row * 68 + c4 * 4;
                d[0] = f2tf(fa[e].x); d[1] = f2tf(fa[e].y);
                d[2] = f2tf(fa[e].z); d[3] = f2tf(fa[e].w);
            }
#pragma unroll
            for (int e = 0; e < 8; ++e) {
                int idx = tid + e * 256, row = idx >> 4, c4 = idx & 15;
                uint32_t* d = W1 + row * 68 + c4 * 4;
                d[0] = f2tf(fw[e].x); d[1] = f2tf(fw[e].y);
                d[2] = f2tf(fw[e].z); d[3] = f2tf(fw[e].w);
            }
        }
        __syncthreads();
    }
#pragma unroll
    for (int mt = 0; mt < 4; ++mt) {
#pragma unroll
        for (int nt = 0; nt < 2; ++nt) {
            int brow = mt * 16 + gid;
            int m = m0 + wid * 16 + nt * 8 + 2 * tig;
            float* base0 = &g_part[((size_t)ks * BATCH + brow) * NLIN + m];
            float* base1 = &g_part[((size_t)ks * BATCH + brow + 8) * NLIN + m];
            *(float2*)base0 = make_float2(acc[mt][nt][0], acc[mt][nt][1]);
            *(float2*)base1 = make_float2(acc[mt][nt][2], acc[mt][nt][3]);
        }
    }
}

// ---------------- tensor-core LSTM recurrence ----------------
// 128 blocks x 256 threads. Block bk owns h-cols [4bk,4bk+4) => 16 gate rows.
// W frags (hi/lo, frag-major) built once in smem. Per step: stage h hi/lo in
// two K=256 chunks (chunk1 LDG prefetched under chunk0 mma), 3-term tf32 mma,
// k-half reduce, epilogue activations, 8-counter grid barrier.
__device__ __forceinline__ void lstm_mma(
    const float* __restrict__ Whh,
    const float* __restrict__ pre, int preStride,
    float* __restrict__ hPing, float* __restrict__ hPong,
    float* __restrict__ cbuf, int loadC, int saveC,
    float* __restrict__ seqOut, int nsteps)
{
    extern __shared__ __align__(16) uint32_t sm[];
    uint32_t* wsf = sm;
    uint32_t* Ahi = sm + AHI_OFF;
    uint32_t* Alo = sm + ALO_OFF;
    float* Csm = (float*)(sm + CSM_OFF);
    float* red = (float*)(sm + RED_OFF);

    const int tid = threadIdx.x;
    const int bk = blockIdx.x;
    const int hc0 = bk * 4;
    const int lane = tid & 31, wid = tid >> 5;
    const int mg = wid >> 1, kh = wid & 1;
    const int gid = lane >> 2, tig = lane & 3;
    const int b = tid & 63, chn = (tid >> 6) & 3;
    const int hcol = hc0 + chn;

    // Build W frags: fragId = (ktg*2+nt)*2+term, 64 u32 each (lane*2+reg)
    for (int idx = tid; idx < 16384; idx += 256) {
        int fragId = idx >> 6, rem = idx & 63;
        int ln = rem >> 1, rg = rem & 1;
        int ktg = fragId >> 2, nt = (fragId >> 1) & 1, term = fragId & 1;
        int g2 = ln >> 2, t2 = ln & 3;
        int r = nt * 8 + g2;
        int q = r >> 2, cc = r & 3;
        int k = ktg * 8 + t2 + 4 * rg;
        float w = Whh[(size_t)(q * HID + hc0 + cc) * HID + k];
        uint32_t hi = f2tf(w);
        wsf[idx] = term == 0 ? hi : f2tf(w - __uint_as_float(hi));
    }
    __syncthreads();

    float creg = loadC ? cbuf[b * HID + hcol] : 0.0f;

    for (int t = 0; t < nsteps; ++t) {
        const float* hin = (t & 1) ? hPong : hPing;
        float* hout = (t & 1) ? hPing : hPong;

        float p0, p1, p2, p3;
        {
            const float* pp = pre + (size_t)t * preStride + b * G4 + hcol;
            p0 = __ldg(pp); p1 = __ldg(pp + 512);
            p2 = __ldg(pp + 1024); p3 = __ldg(pp + 1536);
        }

        float acc[2][4];
#pragma unroll
        for (int nt = 0; nt < 2; ++nt)
#pragma unroll
            for (int r = 0; r < 4; ++r) acc[nt][r] = 0.0f;

        // ---- stage chunk 0 ----
        float4 v[16];
#pragma unroll
        for (int e = 0; e < 16; ++e) {
            int idx = tid + e * 256;
            int row = idx >> 6, f4 = idx & 63;
            v[e] = __ldcg((const float4*)(hin + row * 512 + f4 * 4));
        }
#pragma unroll
        for (int e = 0; e < 16; ++e) {
            int idx = tid + e * 256;
            int row = idx >> 6, f4 = idx & 63;
            uint32_t h0 = f2tf(v[e].x), h1 = f2tf(v[e].y),
                     h2 = f2tf(v[e].z), h3 = f2tf(v[e].w);
            *(uint4*)(Ahi + row * 260 + f4 * 4) = make_uint4(h0, h1, h2, h3);
            *(uint4*)(Alo + row * 260 + f4 * 4) = make_uint4(
                f2tf(v[e].x - __uint_as_float(h0)),
                f2tf(v[e].y - __uint_as_float(h1)),
                f2tf(v[e].z - __uint_as_float(h2)),
                f2tf(v[e].w - __uint_as_float(h3)));
        }
        // prefetch chunk 1 into regs (in flight under chunk-0 mma)
        float4 v2[16];
#pragma unroll
        for (int e = 0; e < 16; ++e) {
            int idx = tid + e * 256;
            int row = idx >> 6, f4 = idx & 63;
            v2[e] = __ldcg((const float4*)(hin + row * 512 + 256 + f4 * 4));
        }
        __syncthreads();

#pragma unroll 1
        for (int ck = 0; ck < 2; ++ck) {
#pragma unroll
            for (int kt = 0; kt < 16; ++kt) {
                int ktc = kh * 16 + kt;           // k-tile within chunk
                int ktg = ck * 32 + ktc;          // global k-tile
                int abase = (mg * 16 + gid) * 260 + ktc * 8 + tig;
                uint32_t ah[4], al[4];
                ah[0] = Ahi[abase];           ah[1] = Ahi[abase + 8 * 260];
                ah[2] = Ahi[abase + 4];       ah[3] = Ahi[abase + 8 * 260 + 4];
                al[0] = Alo[abase];           al[1] = Alo[abase + 8 * 260];
                al[2] = Alo[abase + 4];       al[3] = Alo[abase + 8 * 260 + 4];
#pragma unroll
                for (int nt = 0; nt < 2; ++nt) {
                    int fb = ((ktg * 2 + nt) * 2) * 64 + lane * 2;
                    uint32_t bh[2], bl[2];
                    *(uint2*)bh = *(const uint2*)(wsf + fb);
                    *(uint2*)bl = *(const uint2*)(wsf + fb + 64);
                    mma_tf32(acc[nt], ah, bh);
                    mma_tf32(acc[nt], ah, bl);
                    mma_tf32(acc[nt], al, bh);
                }
            }
            __syncthreads();
            if (ck == 0) {   // stage chunk 1 from prefetched regs
#pragma unroll
                for (int e = 0; e < 16; ++e) {
                    int idx = tid + e * 256;
                    int row = idx >> 6, f4 = idx & 63;
                    uint32_t h0 = f2tf(v2[e].x), h1 = f2tf(v2[e].y),
                             h2 = f2tf(v2[e].z), h3 = f2tf(v2[e].w);
                    *(uint4*)(Ahi + row * 260 + f4 * 4) = make_uint4(h0, h1, h2, h3);
                    *(uint4*)(Alo + row * 260 + f4 * 4) = make_uint4(
                        f2tf(v2[e].x - __uint_as_float(h0)),
                        f2tf(v2[e].y - __uint_as_float(h1)),
                        f2tf(v2[e].z - __uint_as_float(h2)),
                        f2tf(v2[e].w - __uint_as_float(h3)));
                }
                __syncthreads();
            }
        }

        // ---- k-half reduce + C tile ----
        if (kh == 1) {
#pragma unroll
            for (int nt = 0; nt < 2; ++nt)
                *(float4*)(red + (mg * 32 + lane) * 8 + nt * 4) =
                    make_float4(acc[nt][0], acc[nt][1], acc[nt][2], acc[nt][3]);
        }
        __syncthreads();
        if (kh == 0) {
#pragma unroll
            for (int nt = 0; nt < 2; ++nt) {
                float4 r4 = *(const float4*)(red + (mg * 32 + lane) * 8 + nt * 4);
                float c0 = acc[nt][0] + r4.x, c1 = acc[nt][1] + r4.y;
                float c2 = acc[nt][2] + r4.z, c3 = acc[nt][3] + r4.w;
                int row = mg * 16 + gid, col = nt * 8 + 2 * tig;
                Csm[row * 17 + col] = c0;
                Csm[row * 17 + col + 1] = c1;
                Csm[(row + 8) * 17 + col] = c2;
                Csm[(row + 8) * 17 + col + 1] = c3;
            }
        }
        __syncthreads();

        // ---- epilogue: gates i,f,g,o at cols q*4+chn ----
        {
            float a0 = Csm[b * 17 + 0 + chn] + p0;
            float a1 = Csm[b * 17 + 4 + chn] + p1;
            float a2 = Csm[b * 17 + 8 + chn] + p2;
            float a3 = Csm[b * 17 + 12 + chn] + p3;
            float si = 1.0f / (1.0f + __expf(-a0));
            float sf = 1.0f / (1.0f + __expf(-a1));
            float so = 1.0f / (1.0f + __expf(-a3));
            creg = sf * creg + si * tanhf(a2);
            float hnew = so * tanhf(creg);
            hout[b * HID + hcol] = hnew;
            if (seqOut) seqOut[(size_t)b * KLIN + t * HID + hcol] = hnew;
        }
        __syncthreads();

        // ---- grid barrier (8-counter fan-in; counters pre-zeroed) ----
        if (t + 1 < nsteps) {
            if (tid == 0) {
                __threadfence();
                atomicAdd(&g_ctr[bk & 7], 1u);
                unsigned need = 16u * (unsigned)(t + 1);
                for (;;) {
                    bool ok = true;
#pragma unroll
                    for (int i = 0; i < 8; ++i) {
                        unsigned cv = *(volatile unsigned*)&g_ctr[i];
                        if (cv < need) { ok = false; break; }
                    }
                    if (ok) break;
                    __nanosleep(64);
                }
                __threadfence();
            }
            __syncthreads();
        }
    }
    if (saveC) cbuf[b * HID + hcol] = creg;
}

__global__ void __launch_bounds__(256, 1) k_enc(const float* __restrict__ Whh) {
    lstm_mma(Whh, g_pre1, BATCH * G4, g_hA, g_hB, g_c, 0, 1, nullptr, TIN);
}
__global__ void __launch_bounds__(256, 1) k_dec(const float* __restrict__ Whh) {
    lstm_mma(Whh, g_pre2, 0, g_hA, g_hB, g_c, 1, 0, g_seq, TOUTN);
}

extern "C" void kernel_launch(void* const* d_in, const int* in_sizes, int n_in,
                              void* d_out, int out_size) {
    const float* x    = (const float*)d_in[0];
    const float* Wih1 = (const float*)d_in[1];
    const float* Whh1 = (const float*)d_in[2];
    const float* bih1 = (const float*)d_in[3];
    const float* bhh1 = (const float*)d_in[4];
    const float* Wih2 = (const float*)d_in[5];
    const float* Whh2 = (const float*)d_in[6];
    const float* bih2 = (const float*)d_in[7];
    const float* bhh2 = (const float*)d_in[8];
    const float* Wlin = (const float*)d_in[9];
    const float* blin = (const float*)d_in[10];
    float* out = (float*)d_out;

    const int lstmSmem = DSMW * 4;        // 207104
    const int linSmem  = 2 * 13056 * 4;   // 104448
    cudaFuncSetAttribute(k_enc, cudaFuncAttributeMaxDynamicSharedMemorySize, lstmSmem);
    cudaFuncSetAttribute(k_dec, cudaFuncAttributeMaxDynamicSharedMemorySize, lstmSmem);
    cudaFuncSetAttribute(k_lin_mma, cudaFuncAttributeMaxDynamicSharedMemorySize, linSmem);

    k_xt<<<(TIN * BATCH * FIN + 255) / 256, 256>>>(x);
    k_init<<<(BATCH * HID + 255) / 256, 256>>>();

    dim3 gpre1(G4 / 64, 1, (TIN * BATCH) / 64);
    k_pre1<<<gpre1, 256>>>(Wih1, bih1, bhh1);

    k_enc<<<NBLK, 256, lstmSmem>>>(Whh1);   // TIN even: final h in g_hA, c in g_c

    dim3 gpre2(G4 / 64, 1, 1);
    k_pre2<<<gpre2, 256>>>(Wih2, bih2, bhh2);

    k_zero<<<1, 32>>>();
    k_dec<<<NBLK, 256, lstmSmem>>>(Whh2);

    dim3 glin(NLIN / 128, KSPLIT);
    k_lin_mma<<<glin, 256, linSmem>>>(Wlin);

    k_combine<<<(BATCH * NLIN + 255) / 256, 256>>>(blin, out);
}